// round 6
// baseline (speedup 1.0000x reference)
#include <cuda_runtime.h>
#include <cstdint>

#define Bdim 32
#define Kdim 17
#define Hdim 160
#define Wdim 160
#define HW   (Hdim*Wdim)
#define W4   (Wdim/4)
#define NG   (HW/4)
#define Pn   30
#define Sn   10
#define Ln   19
#define NCH  (Bdim*Kdim)
#define T1   320
#define RPT  20
#define T2   512
#define NBINS 1024
#define SCAP  256
#define NEGF  (-1.0e30f)

__constant__ int c_skel_a[Ln] = {15,13,16,14,11, 5, 6, 5, 5, 6, 7, 8, 1, 0, 0, 1, 2, 3, 4};
__constant__ int c_skel_b[Ln] = {13,11,14,12,12,11,12, 6, 7, 8, 9,10, 2, 1, 2, 3, 4, 5, 6};

// ---------------- cp.async helpers ----------------
__device__ __forceinline__ void cp16(void* s, const void* g) {
    unsigned sa = (unsigned)__cvta_generic_to_shared(s);
    asm volatile("cp.async.cg.shared.global [%0], [%1], 16;\n" :: "r"(sa), "l"(g));
}
__device__ __forceinline__ void cp_commit() { asm volatile("cp.async.commit_group;\n"); }
template <int N>
__device__ __forceinline__ void cp_wait() { asm volatile("cp.async.wait_group %0;\n" :: "n"(N)); }

// monotone bin: v = h^9 (uniform-izes max-of-9 peak-score distribution)
__device__ __forceinline__ int bin_of(float h) {
    float h2 = h * h;
    float h4 = h2 * h2;
    float v  = h4 * h4 * h;
    int b = (int)(v * (float)NBINS);
    return b < 0 ? 0 : (b > NBINS - 1 ? NBINS - 1 : b);
}

__device__ __forceinline__ float max3(float a, float b, float c) {
    return fmaxf(fmaxf(a, b), c);
}

// load one image row segment (4 px) + left/right halo scalars.
// halos come from neighbor lanes via shuffle; warp-boundary lanes fall back to
// a scalar load (L1 hit).  OOB row or OOB column -> NEGF.
__device__ __forceinline__ void loadrow(const float* __restrict__ hp,
                                        const float4* __restrict__ hp4,
                                        int y, bool has_l, bool has_r,
                                        int lane, int ibase,
                                        float4& R, float& lH, float& rH)
{
    bool yv = (y >= 0) && (y < Hdim);
    float4 nf = make_float4(NEGF, NEGF, NEGF, NEGF);
    R = yv ? hp4[y * W4 + (ibase >> 2)] : nf;
    float ls = __shfl_up_sync(0xffffffffu, R.w, 1);      // converged: all lanes
    float rs = __shfl_down_sync(0xffffffffu, R.x, 1);
    lH = NEGF; rH = NEGF;
    if (yv && has_l) lH = (lane > 0)  ? ls : __ldg(hp + y * Wdim + ibase - 1);
    if (yv && has_r) rH = (lane < 31) ? rs : __ldg(hp + y * Wdim + ibase + 4);
}

// detect 4 px from the 3-row register window; histogram peaks; return pattern
__device__ __forceinline__ unsigned detect4w(float4 U, float lU, float rU,
                                             float4 C, float lC, float rC,
                                             float4 D, float lD, float rD,
                                             unsigned* hist)
{
    float wU[6] = {lU, U.x, U.y, U.z, U.w, rU};
    float wC[6] = {lC, C.x, C.y, C.z, C.w, rC};
    float wD[6] = {lD, D.x, D.y, D.z, D.w, rD};
    unsigned pat = 0;
    #pragma unroll
    for (int j = 0; j < 4; ++j) {
        float h  = wC[j + 1];
        float nm = fmaxf(max3(wU[j], wU[j + 1], wU[j + 2]),
                         fmaxf(max3(wD[j], wD[j + 1], wD[j + 2]),
                               fmaxf(wC[j], wC[j + 2])));
        bool pk = (h > 0.1f) && (nm <= h);
        if (pk) {
            pat |= (1u << j);
            atomicAdd(&hist[bin_of(h)], 1u);
        }
    }
    return pat;
}

// ---------------------------------------------------------------------------
// Stage 1: one block per (b,k) channel.  8 strips x 40 threads; each thread
// sweeps a 4-wide column down 20 rows with register rotation (1 vec load/row).
// ---------------------------------------------------------------------------
__global__ void __launch_bounds__(T1) stage1_kernel(const float* __restrict__ heat,
                                                    float* __restrict__ out_peaks)
{
    __shared__ unsigned hist[NBINS];
    __shared__ unsigned long long surv[SCAP];
    __shared__ unsigned long long s_top[Pn];
    __shared__ int s_sc, s_cut;

    const int ch = blockIdx.x;
    const float* hp = heat + (size_t)ch * HW;
    const float4* hp4 = (const float4*)hp;
    const int tid = threadIdx.x;
    const int lane = tid & 31;
    const int strip = tid / W4;            // 0..7
    const int xq = tid - strip * W4;       // 0..39
    const int ibase = xq * 4;
    const int y0 = strip * RPT;
    const bool has_l = (xq > 0);
    const bool has_r = (xq < W4 - 1);

    for (int i = tid; i < NBINS; i += T1) hist[i] = 0;
    if (tid == 0) { s_sc = 0; s_cut = 0; }
    __syncthreads();

    // ---- pass 1: rolling 3-row window down the strip ----
    float4 U, C, D;
    float lU, rU, lC, rC, lD, rD;
    loadrow(hp, hp4, y0 - 1, has_l, has_r, lane, ibase, U, lU, rU);
    loadrow(hp, hp4, y0,     has_l, has_r, lane, ibase, C, lC, rC);

    unsigned w0 = 0, w1 = 0, w2 = 0;
    #pragma unroll
    for (int it = 0; it < 8; ++it) {
        loadrow(hp, hp4, y0 + it + 1, has_l, has_r, lane, ibase, D, lD, rD);
        w0 |= detect4w(U, lU, rU, C, lC, rC, D, lD, rD, hist) << (it * 4);
        U = C; lU = lC; rU = rC;
        C = D; lC = lD; rC = rD;
    }
    #pragma unroll
    for (int it = 8; it < 16; ++it) {
        loadrow(hp, hp4, y0 + it + 1, has_l, has_r, lane, ibase, D, lD, rD);
        w1 |= detect4w(U, lU, rU, C, lC, rC, D, lD, rD, hist) << ((it - 8) * 4);
        U = C; lU = lC; rU = rC;
        C = D; lC = lD; rC = rD;
    }
    #pragma unroll
    for (int it = 16; it < RPT; ++it) {
        loadrow(hp, hp4, y0 + it + 1, has_l, has_r, lane, ibase, D, lD, rD);
        w2 |= detect4w(U, lU, rU, C, lC, rC, D, lD, rD, hist) << ((it - 16) * 4);
        U = C; lU = lC; rU = rC;
        C = D; lC = lD; rC = rD;
    }
    __syncthreads();

    // ---- warp 0: cutoff bin = highest bin whose suffix count >= Pn ----
    if (tid < 32) {
        int acc = 0, cut = 0;
        for (int base = NBINS - 32; base >= 0; base -= 32) {
            int s = (int)hist[base + lane];
            #pragma unroll
            for (int off = 1; off < 32; off <<= 1) {
                int t = __shfl_down_sync(0xffffffffu, s, off);
                if (lane + off < 32) s += t;
            }
            int chunk_total = __shfl_sync(0xffffffffu, s, 0);
            if (acc + chunk_total >= Pn) {
                unsigned msk = __ballot_sync(0xffffffffu, acc + s >= Pn);
                cut = base + (31 - __clz(msk));
                break;
            }
            acc += chunk_total;
        }
        if (lane == 0) s_cut = cut;
    }
    __syncthreads();

    // ---- pass 2: replay bitmask, keep bins >= cut (rare -> plain atomics) ----
    const int cut = s_cut;
    unsigned mw[3] = {w0, w1, w2};
    #pragma unroll
    for (int w = 0; w < 3; ++w) {
        unsigned m = mw[w];
        while (m) {
            int b = __ffs(m) - 1;
            m &= m - 1;
            int bitidx = w * 32 + b;
            int it = bitidx >> 2;
            int j  = bitidx & 3;
            int i  = (y0 + it) * Wdim + ibase + j;
            float h = __ldg(hp + i);
            if (bin_of(h) >= cut) {
                int pos = atomicAdd(&s_sc, 1);
                if (pos < SCAP) {
                    surv[pos] = ((unsigned long long)__float_as_uint(h) << 32) |
                                (unsigned long long)(0xFFFFFFFFu - (unsigned)i);
                }
            }
        }
    }
    __syncthreads();

    // ---- warp 0: 30 argmax rounds + subpixel refine ----
    if (tid < 32) {
        const int n = (s_sc < SCAP) ? s_sc : SCAP;
        for (int p = 0; p < Pn; ++p) {
            unsigned long long best = 0ull;
            int bpos = -1;
            for (int i = lane; i < n; i += 32) {
                unsigned long long c = surv[i];
                if (c > best) { best = c; bpos = i; }
            }
            #pragma unroll
            for (int off = 16; off > 0; off >>= 1) {
                unsigned long long ob = __shfl_down_sync(0xffffffffu, best, off);
                int op = __shfl_down_sync(0xffffffffu, bpos, off);
                if (ob > best) { best = ob; bpos = op; }
            }
            best = __shfl_sync(0xffffffffu, best, 0);
            bpos = __shfl_sync(0xffffffffu, bpos, 0);
            if (lane == 0) {
                s_top[p] = best;
                if (bpos >= 0) surv[bpos] = 0ull;
            }
            __syncwarp();
        }

        if (lane < Pn) {
            unsigned long long key = s_top[lane];
            float px = 0.f, py = 0.f, sc = 0.f;
            if (key != 0ull) {
                unsigned idx = 0xFFFFFFFFu - (unsigned)(key & 0xFFFFFFFFu);
                float h = __uint_as_float((unsigned)(key >> 32));
                int y = idx / Wdim;
                int x = idx - y * Wdim;
                float dx = 0.f, dy = 0.f;
                if (y > 0 && y < Hdim - 1 && x > 0 && x < Wdim - 1) {
                    float r = __ldg(hp + idx + 1),    l = __ldg(hp + idx - 1);
                    float d = __ldg(hp + idx + Wdim), u = __ldg(hp + idx - Wdim);
                    float dxr = 0.5f * (r - l);
                    float dxx = (r + l) - 2.0f * h;
                    dx = (fabsf(dxx) > 1e-6f) ? (dxr / (-dxx)) : dxr;
                    float dyr = 0.5f * (d - u);
                    float dyy = (d + u) - 2.0f * h;
                    dy = (fabsf(dyy) > 1e-6f) ? (dyr / (-dyy)) : dyr;
                }
                px = (float)x + dx;
                py = (float)y + dy;
                sc = h;
            }
            float* o = out_peaks + ((size_t)ch * Pn + lane) * 3;
            o[0] = px; o[1] = py; o[2] = sc;
        }
    }
}

// ---------------------------------------------------------------------------
// Stage 2: per-(b,l) limb — one PAF channel in smem at a time (100KB) so two
// blocks co-reside per SM and loads overlap compute across blocks.
// ---------------------------------------------------------------------------
__global__ void __launch_bounds__(T2, 2) stage2_kernel(const float* __restrict__ paf,
                                                       const float* __restrict__ peaks,
                                                       float* __restrict__ conn)
{
    extern __shared__ float s2[];                // HW floats (reused x then y)

    __shared__ float sax[Pn], say[Pn], sas[Pn];
    __shared__ float sbx[Pn], sby[Pn], sbs[Pn];

    const int bl = blockIdx.x;      // b*Ln + l
    const int b = bl / Ln;
    const int l = bl - b * Ln;

    const float4* gx = (const float4*)(paf + ((size_t)b * 38 + 2 * l) * HW);
    const float4* gy = (const float4*)(paf + ((size_t)b * 38 + 2 * l + 1) * HW);

    for (int i = threadIdx.x; i < NG; i += T2)
        cp16(&((float4*)s2)[i], &gx[i]);
    cp_commit();

    const int ja = c_skel_a[l];
    const int jb = c_skel_b[l];
    if (threadIdx.x < Pn) {
        const float* pa = peaks + ((size_t)(b * Kdim + ja) * Pn + threadIdx.x) * 3;
        sax[threadIdx.x] = pa[0]; say[threadIdx.x] = pa[1]; sas[threadIdx.x] = pa[2];
    } else if (threadIdx.x >= 32 && threadIdx.x < 32 + Pn) {
        int j = threadIdx.x - 32;
        const float* pb = peaks + ((size_t)(b * Kdim + jb) * Pn + j) * 3;
        sbx[j] = pb[0]; sby[j] = pb[1]; sbs[j] = pb[2];
    }

    cp_wait<0>();
    __syncthreads();

    int   lin[2][Sn];
    float xp [2][Sn];
    float vyv[2];
    float halfs[2];
    bool  pv[2];
    const float step = 1.0f / 9.0f;

    #pragma unroll
    for (int q = 0; q < 2; ++q) {
        int pr = threadIdx.x + q * T2;
        bool act = (pr < Pn * Pn);
        int i = act ? (pr / Pn) : 0;
        int j = act ? (pr - i * Pn) : 0;
        float ax = sax[i], ay = say[i], sa = sas[i];
        float bx = sbx[j], by = sby[j], sb = sbs[j];
        bool valid = act && (sa > 0.1f) && (sb > 0.1f);
        pv[q] = valid;
        halfs[q] = 0.5f * (sa + sb);
        float dxl = bx - ax;
        float dyl = by - ay;
        float norm = sqrtf(__fadd_rn(__fmul_rn(dxl, dxl), __fmul_rn(dyl, dyl))) + 1e-8f;
        float vx = dxl / norm;
        float vy = dyl / norm;
        vyv[q] = vy;
        #pragma unroll
        for (int s = 0; s < Sn; ++s) {
            float t = (float)s * step;
            // no-FMA: a ulp flip at a .5 boundary changes the gathered cell
            float xs = __fadd_rn(ax, __fmul_rn(t, dxl));
            float ys = __fadd_rn(ay, __fmul_rn(t, dyl));
            float fx = fminf(fmaxf(rintf(xs), 0.0f), (float)(Wdim - 1));
            float fy = fminf(fmaxf(rintf(ys), 0.0f), (float)(Hdim - 1));
            int li = valid ? ((int)fy * Wdim + (int)fx) : 0;
            lin[q][s] = li;
            xp[q][s] = __fmul_rn(s2[li], vx);
        }
    }
    __syncthreads();                 // all pafx reads done; buffer free

    for (int i = threadIdx.x; i < NG; i += T2)
        cp16(&((float4*)s2)[i], &gy[i]);
    cp_commit();
    cp_wait<0>();
    __syncthreads();

    float* co = conn + (size_t)bl * Pn * Pn;
    #pragma unroll
    for (int q = 0; q < 2; ++q) {
        int pr = threadIdx.x + q * T2;
        bool act = (pr < Pn * Pn);
        float sum = 0.0f;
        int c = 0;
        #pragma unroll
        for (int s = 0; s < Sn; ++s) {
            float v = __fadd_rn(xp[q][s], __fmul_rn(s2[lin[q][s]], vyv[q]));
            sum = __fadd_rn(sum, v);
            c += (v > 0.05f) ? 1 : 0;
        }
        float outv = 0.0f;
        if (pv[q]) {
            float mean = sum / 10.0f;
            float ratio = (float)c / 10.0f;
            if (mean > 0.0f && ratio > 0.8f)
                outv = mean + halfs[q];
        }
        if (act) co[pr] = outv;
    }
}

// ---------------------------------------------------------------------------
extern "C" void kernel_launch(void* const* d_in, const int* in_sizes, int n_in,
                              void* d_out, int out_size)
{
    const float* heat = (const float*)d_in[0];
    const float* paf  = (const float*)d_in[1];
    float* out   = (float*)d_out;
    float* peaks = out;                                  // B*K*P*3 = 48960
    float* conn  = out + (size_t)Bdim * Kdim * Pn * 3;   // B*L*P*P = 547200

    const int smem2 = HW * 4;                            // 102400 -> 2 blocks/SM
    cudaFuncSetAttribute(stage2_kernel, cudaFuncAttributeMaxDynamicSharedMemorySize, smem2);

    stage1_kernel<<<NCH, T1>>>(heat, peaks);
    stage2_kernel<<<Bdim * Ln, T2, smem2>>>(paf, peaks, conn);
}